// round 1
// baseline (speedup 1.0000x reference)
#include <cuda_runtime.h>

#define D        32000
#define D4       (D / 4)          // 8000 float4 per row
#define THREADS  1024
#define NV4      8                // float4 slots per thread (ceil(8000/1024))
#define NE       32               // float slots per thread
#define MAX_ITER 100
#define TOL      1e-5f
// hi = max_val - gp(1/d) = max_val + 2 - 2*sqrt(1/32000)
#define HI_OFFSET 1.9888196601125011f
#define NEG_BIG  -1e30f

__device__ __forceinline__ float warp_reduce_sum(float v) {
#pragma unroll
    for (int o = 16; o; o >>= 1) v += __shfl_xor_sync(0xffffffffu, v, o);
    return v;
}

__device__ __forceinline__ float warp_reduce_max(float v) {
#pragma unroll
    for (int o = 16; o; o >>= 1) v = fmaxf(v, __shfl_xor_sync(0xffffffffu, v, o));
    return v;
}

__global__ void __launch_bounds__(THREADS, 1)
tsallis_secant_kernel(const float* __restrict__ X, float* __restrict__ Y) {
    __shared__ float red[32];
    __shared__ float bc;

    const int tid  = threadIdx.x;
    const int lane = tid & 31;
    const int wid  = tid >> 5;
    const size_t row = blockIdx.x;

    const float4* __restrict__ x4 = reinterpret_cast<const float4*>(X) + row * D4;
    float4* __restrict__       y4 = reinterpret_cast<float4*>(Y) + row * D4;

    // ---- load row into registers (coalesced float4, strided by blockDim) ----
    float xv[NE];
#pragma unroll
    for (int k = 0; k < NV4; k++) {
        const int i4 = tid + k * THREADS;
        if (k < NV4 - 1 || i4 < D4) {
            float4 v = __ldg(&x4[i4]);
            xv[4 * k + 0] = v.x;
            xv[4 * k + 1] = v.y;
            xv[4 * k + 2] = v.z;
            xv[4 * k + 3] = v.w;
        } else {
            // padding: p(pad) = (1 + 0.5*max(pad - tau, -2))^2 = 0 exactly
            xv[4 * k + 0] = NEG_BIG;
            xv[4 * k + 1] = NEG_BIG;
            xv[4 * k + 2] = NEG_BIG;
            xv[4 * k + 3] = NEG_BIG;
        }
    }

    // ---- row max (block reduction) ----
    float m = NEG_BIG;
#pragma unroll
    for (int k = 0; k < NE; k++) m = fmaxf(m, xv[k]);
    m = warp_reduce_max(m);
    if (lane == 0) red[wid] = m;
    __syncthreads();
    if (wid == 0) {
        float t = warp_reduce_max(red[lane]);
        if (lane == 0) bc = t;
    }
    __syncthreads();
    const float max_val = bc;

    // ---- eval: sum_i (max(1 + 0.5*(x_i - tau), 0))^2 over the row ----
    auto eval = [&](float tau) -> float {
        const float c2 = fmaf(-0.5f, tau, 1.0f);  // 1 - 0.5*tau
        float a0 = 0.f, a1 = 0.f, a2 = 0.f, a3 = 0.f;
#pragma unroll
        for (int k = 0; k < NE; k += 4) {
            float v0 = fmaxf(fmaf(0.5f, xv[k + 0], c2), 0.0f);
            float v1 = fmaxf(fmaf(0.5f, xv[k + 1], c2), 0.0f);
            float v2 = fmaxf(fmaf(0.5f, xv[k + 2], c2), 0.0f);
            float v3 = fmaxf(fmaf(0.5f, xv[k + 3], c2), 0.0f);
            a0 = fmaf(v0, v0, a0);
            a1 = fmaf(v1, v1, a1);
            a2 = fmaf(v2, v2, a2);
            a3 = fmaf(v3, v3, a3);
        }
        float s = (a0 + a1) + (a2 + a3);
        s = warp_reduce_sum(s);
        if (lane == 0) red[wid] = s;
        __syncthreads();
        if (wid == 0) {
            float t = warp_reduce_sum(red[lane]);
            if (lane == 0) bc = t;
        }
        __syncthreads();
        return bc;  // all threads see identical value -> uniform control flow
    };

    // ---- secant with early exit (bit-equivalent to reference's masked loop:
    //      once (f_lo-f_hi)^2 < tol, the reference carry is frozen forever) ----
    float lo = max_val;                  // gp(1.0) = 0
    float hi = max_val + HI_OFFSET;      // -gp(1/d)

    float f_lo = eval(lo) - 1.0f;
    float f_hi = eval(hi) - 1.0f;

#pragma unroll 1
    for (int it = 0; it < MAX_ITER; it++) {
        const float diff = f_lo - f_hi;
        if (diff * diff < TOL) break;
        const float tau = (lo * f_hi - hi * f_lo) / (f_hi - f_lo);
        lo = hi;
        f_lo = f_hi;
        hi = tau;
        f_hi = eval(hi) - 1.0f;
    }

    // ---- write p(X - hi) ----
    const float c2 = fmaf(-0.5f, hi, 1.0f);
#pragma unroll
    for (int k = 0; k < NV4; k++) {
        const int i4 = tid + k * THREADS;
        if (k < NV4 - 1 || i4 < D4) {
            float v0 = fmaxf(fmaf(0.5f, xv[4 * k + 0], c2), 0.0f);
            float v1 = fmaxf(fmaf(0.5f, xv[4 * k + 1], c2), 0.0f);
            float v2 = fmaxf(fmaf(0.5f, xv[4 * k + 2], c2), 0.0f);
            float v3 = fmaxf(fmaf(0.5f, xv[4 * k + 3], c2), 0.0f);
            float4 r;
            r.x = v0 * v0;
            r.y = v1 * v1;
            r.z = v2 * v2;
            r.w = v3 * v3;
            y4[i4] = r;
        }
    }
}

extern "C" void kernel_launch(void* const* d_in, const int* in_sizes, int n_in,
                              void* d_out, int out_size) {
    const float* X = (const float*)d_in[0];
    float* Y = (float*)d_out;
    const int rows = in_sizes[0] / D;
    tsallis_secant_kernel<<<rows, THREADS>>>(X, Y);
}

// round 2
// speedup vs baseline: 1.0515x; 1.0515x over previous
#include <cuda_runtime.h>
#include <cstdint>

#define D         32000
#define D4        (D / 4)            // 8000 float4 per row
#define ROW_BYTES (D * 4)            // 128000 bytes (multiple of 16)
#define THREADS   1024
#define NV4       8                  // float4 slots per thread
#define NE        32
#define MAX_ITER  100
#define TOL       1e-5f
#define HI_OFFSET 1.9888196601125011f   // -gp(1/32000) = 2 - 2/sqrt(32000)
#define NEG_BIG   -1e30f
#define ROWS      4096

__device__ __forceinline__ uint32_t smem_u32(const void* p) {
    uint32_t a;
    asm("{ .reg .u64 t; cvta.to.shared.u64 t, %1; cvt.u32.u64 %0, t; }"
        : "=r"(a) : "l"(p));
    return a;
}

__device__ __forceinline__ void mbar_init(uint32_t mbar, uint32_t count) {
    asm volatile("mbarrier.init.shared.b64 [%0], %1;" :: "r"(mbar), "r"(count) : "memory");
}

__device__ __forceinline__ void tma_prefetch_row(uint32_t dst_smem, const float* src,
                                                 uint32_t mbar) {
    asm volatile("mbarrier.arrive.expect_tx.shared.b64 _, [%0], %1;"
                 :: "r"(mbar), "r"((uint32_t)ROW_BYTES) : "memory");
    asm volatile("cp.async.bulk.shared::cta.global.mbarrier::complete_tx::bytes "
                 "[%0], [%1], %2, [%3];"
                 :: "r"(dst_smem), "l"(src), "r"((uint32_t)ROW_BYTES), "r"(mbar)
                 : "memory");
}

__device__ __forceinline__ void mbar_wait(uint32_t mbar, uint32_t phase) {
    asm volatile(
        "{\n\t"
        ".reg .pred P;\n\t"
        "W%=:\n\t"
        "mbarrier.try_wait.parity.acquire.cta.shared::cta.b64 P, [%0], %1, 0x989680;\n\t"
        "@!P bra W%=;\n\t"
        "}"
        :: "r"(mbar), "r"(phase) : "memory");
}

__device__ __forceinline__ float warp_reduce_sum(float v) {
#pragma unroll
    for (int o = 16; o; o >>= 1) v += __shfl_xor_sync(0xffffffffu, v, o);
    return v;
}

__device__ __forceinline__ float warp_reduce_max(float v) {
#pragma unroll
    for (int o = 16; o; o >>= 1) v = fmaxf(v, __shfl_xor_sync(0xffffffffu, v, o));
    return v;
}

__global__ void __launch_bounds__(THREADS, 1)
tsallis_secant_kernel(const float* __restrict__ X, float* __restrict__ Y) {
    extern __shared__ float buf[];        // D floats: TMA staging buffer
    __shared__ float red[32];
    __shared__ float bc;
    __shared__ __align__(8) uint64_t mbar_storage;

    const int tid  = threadIdx.x;
    const int lane = tid & 31;
    const int wid  = tid >> 5;

    const uint32_t mbar    = smem_u32(&mbar_storage);
    const uint32_t buf_u32 = smem_u32(buf);

    if (tid == 0) mbar_init(mbar, 1);
    __syncthreads();

    int row = blockIdx.x;
    const int stride = gridDim.x;

    // prologue: prefetch first row
    if (tid == 0 && row < ROWS) {
        tma_prefetch_row(buf_u32, X + (size_t)row * D, mbar);
    }
    uint32_t phase = 0;

    for (; row < ROWS; row += stride) {
        // ---- wait for this row's TMA ----
        mbar_wait(mbar, phase);
        phase ^= 1;

        // ---- SMEM -> registers (coalesced float4), fused with row max ----
        float xv[NE];
        float m = NEG_BIG;
        const float4* b4 = reinterpret_cast<const float4*>(buf);
#pragma unroll
        for (int k = 0; k < NV4; k++) {
            const int i4 = tid + k * THREADS;
            if (k < NV4 - 1 || i4 < D4) {
                float4 v = b4[i4];
                xv[4 * k + 0] = v.x;
                xv[4 * k + 1] = v.y;
                xv[4 * k + 2] = v.z;
                xv[4 * k + 3] = v.w;
            } else {
                xv[4 * k + 0] = NEG_BIG;
                xv[4 * k + 1] = NEG_BIG;
                xv[4 * k + 2] = NEG_BIG;
                xv[4 * k + 3] = NEG_BIG;
            }
        }
#pragma unroll
        for (int k = 0; k < NE; k++) m = fmaxf(m, xv[k]);

        __syncthreads();   // everyone finished reading buf

        // ---- kick prefetch of next row (overlaps the secant below) ----
        const int nrow = row + stride;
        if (tid == 0 && nrow < ROWS) {
            tma_prefetch_row(buf_u32, X + (size_t)nrow * D, mbar);
        }

        // ---- block max ----
        m = warp_reduce_max(m);
        if (lane == 0) red[wid] = m;
        __syncthreads();
        if (wid == 0) {
            float t = warp_reduce_max(red[lane]);
            if (lane == 0) bc = t;
        }
        __syncthreads();
        const float max_val = bc;

        // ---- eval: sum_i (max(1 + 0.5*(x_i - tau), 0))^2 ----
        auto eval = [&](float tau) -> float {
            const float c2 = fmaf(tau, -0.5f, 1.0f);  // 1 - 0.5*tau
            float a0 = 0.f, a1 = 0.f, a2 = 0.f, a3 = 0.f;
#pragma unroll
            for (int k = 0; k < NE; k += 4) {
                float v0 = fmaxf(fmaf(xv[k + 0], 0.5f, c2), 0.0f);
                float v1 = fmaxf(fmaf(xv[k + 1], 0.5f, c2), 0.0f);
                float v2 = fmaxf(fmaf(xv[k + 2], 0.5f, c2), 0.0f);
                float v3 = fmaxf(fmaf(xv[k + 3], 0.5f, c2), 0.0f);
                a0 = fmaf(v0, v0, a0);
                a1 = fmaf(v1, v1, a1);
                a2 = fmaf(v2, v2, a2);
                a3 = fmaf(v3, v3, a3);
            }
            float s = (a0 + a1) + (a2 + a3);
            s = warp_reduce_sum(s);
            if (lane == 0) red[wid] = s;
            __syncthreads();
            if (wid == 0) {
                float t = warp_reduce_sum(red[lane]);
                if (lane == 0) bc = t;
            }
            __syncthreads();
            return bc;
        };

        // ---- secant w/ early exit (matches reference's frozen-carry mask) ----
        float lo = max_val;                  // gp(1.0) = 0
        float hi = max_val + HI_OFFSET;

        float f_lo = eval(lo) - 1.0f;
        float f_hi = eval(hi) - 1.0f;

#pragma unroll 1
        for (int it = 0; it < MAX_ITER; it++) {
            const float diff = f_lo - f_hi;
            if (diff * diff < TOL) break;
            const float tau = (lo * f_hi - hi * f_lo) / (f_hi - f_lo);
            lo = hi;
            f_lo = f_hi;
            hi = tau;
            f_hi = eval(hi) - 1.0f;
        }

        // ---- write p(X - hi) with streaming stores ----
        float4* y4 = reinterpret_cast<float4*>(Y) + (size_t)row * D4;
        const float c2 = fmaf(hi, -0.5f, 1.0f);
#pragma unroll
        for (int k = 0; k < NV4; k++) {
            const int i4 = tid + k * THREADS;
            if (k < NV4 - 1 || i4 < D4) {
                float v0 = fmaxf(fmaf(xv[4 * k + 0], 0.5f, c2), 0.0f);
                float v1 = fmaxf(fmaf(xv[4 * k + 1], 0.5f, c2), 0.0f);
                float v2 = fmaxf(fmaf(xv[4 * k + 2], 0.5f, c2), 0.0f);
                float v3 = fmaxf(fmaf(xv[4 * k + 3], 0.5f, c2), 0.0f);
                float4 r;
                r.x = v0 * v0;
                r.y = v1 * v1;
                r.z = v2 * v2;
                r.w = v3 * v3;
                __stcs(&y4[i4], r);
            }
        }
        // no __syncthreads needed here: next iteration begins with mbar_wait
    }
}

extern "C" void kernel_launch(void* const* d_in, const int* in_sizes, int n_in,
                              void* d_out, int out_size) {
    const float* X = (const float*)d_in[0];
    float* Y = (float*)d_out;

    static int n_sm = 0;
    if (n_sm == 0) {
        cudaDeviceGetAttribute(&n_sm, cudaDevAttrMultiProcessorCount, 0);
        cudaFuncSetAttribute(tsallis_secant_kernel,
                             cudaFuncAttributeMaxDynamicSharedMemorySize,
                             ROW_BYTES);
    }
    tsallis_secant_kernel<<<n_sm, THREADS, ROW_BYTES>>>(X, Y);
}

// round 4
// speedup vs baseline: 1.1040x; 1.0499x over previous
#include <cuda_runtime.h>
#include <cstdint>

#define D         32000
#define D4        (D / 4)            // 8000 float4 per row
#define ROW_BYTES (D * 4)            // 128000 bytes
#define THREADS   1024
#define NV4       8
#define NE        32
#define MAX_ITER  100
#define TOL       1e-5f
#define HI_OFFSET 1.9888196601125011f   // -gp(1/32000) = 2 - 2/sqrt(32000)
#define NEG_BIG   -1e30f
#define ROWS      4096

__device__ __forceinline__ uint32_t smem_u32(const void* p) {
    uint32_t a;
    asm("{ .reg .u64 t; cvta.to.shared.u64 t, %1; cvt.u32.u64 %0, t; }"
        : "=r"(a) : "l"(p));
    return a;
}

__device__ __forceinline__ void mbar_init(uint32_t mbar, uint32_t count) {
    asm volatile("mbarrier.init.shared.b64 [%0], %1;" :: "r"(mbar), "r"(count) : "memory");
}

__device__ __forceinline__ void tma_prefetch_row(uint32_t dst_smem, const float* src,
                                                 uint32_t mbar) {
    asm volatile("mbarrier.arrive.expect_tx.shared.b64 _, [%0], %1;"
                 :: "r"(mbar), "r"((uint32_t)ROW_BYTES) : "memory");
    asm volatile("cp.async.bulk.shared::cta.global.mbarrier::complete_tx::bytes "
                 "[%0], [%1], %2, [%3];"
                 :: "r"(dst_smem), "l"(src), "r"((uint32_t)ROW_BYTES), "r"(mbar)
                 : "memory");
}

__device__ __forceinline__ void mbar_wait(uint32_t mbar, uint32_t phase) {
    asm volatile(
        "{\n\t"
        ".reg .pred P;\n\t"
        "W%=:\n\t"
        "mbarrier.try_wait.parity.acquire.cta.shared::cta.b64 P, [%0], %1, 0x989680;\n\t"
        "@!P bra W%=;\n\t"
        "}"
        :: "r"(mbar), "r"(phase) : "memory");
}

__device__ __forceinline__ float warp_sum(float v) {
#pragma unroll
    for (int o = 16; o; o >>= 1) v += __shfl_xor_sync(0xffffffffu, v, o);
    return v;
}

__device__ __forceinline__ float warp_max(float v) {
#pragma unroll
    for (int o = 16; o; o >>= 1) v = fmaxf(v, __shfl_xor_sync(0xffffffffu, v, o));
    return v;
}

__global__ void __launch_bounds__(THREADS, 1)
tsallis_secant_kernel(const float* __restrict__ X, float* __restrict__ Y) {
    extern __shared__ float buf[];          // D floats: TMA staging buffer
    __shared__ float red[2][32];            // double-buffered reduction scratch
    __shared__ float2 red2[32];
    __shared__ __align__(8) uint64_t mbar_storage;

    const int tid  = threadIdx.x;
    const int lane = tid & 31;
    const int wid  = tid >> 5;

    const uint32_t mbar    = smem_u32(&mbar_storage);
    const uint32_t buf_u32 = smem_u32(buf);

    if (tid == 0) mbar_init(mbar, 1);
    __syncthreads();

    int rb = 0;  // reduction buffer toggle (uniform across threads)

    // one-sync block sum: every warp re-reduces the 32 partials itself
    auto block_sum = [&](float s) -> float {
        s = warp_sum(s);
        if (lane == 0) red[rb][wid] = s;
        __syncthreads();
        float t = warp_sum(red[rb][lane]);
        rb ^= 1;
        return t;
    };

    int row = blockIdx.x;
    const int stride = gridDim.x;

    if (tid == 0 && row < ROWS) {
        tma_prefetch_row(buf_u32, X + (size_t)row * D, mbar);
    }
    uint32_t phase = 0;

    for (; row < ROWS; row += stride) {
        mbar_wait(mbar, phase);
        phase ^= 1;

        // ---- SMEM -> registers, fused local max ----
        float xv[NE];
        float m = NEG_BIG;
        const float4* b4 = reinterpret_cast<const float4*>(buf);
#pragma unroll
        for (int k = 0; k < NV4; k++) {
            const int i4 = tid + k * THREADS;
            if (k < NV4 - 1 || i4 < D4) {
                float4 v = b4[i4];
                xv[4 * k + 0] = v.x;
                xv[4 * k + 1] = v.y;
                xv[4 * k + 2] = v.z;
                xv[4 * k + 3] = v.w;
            } else {
                xv[4 * k + 0] = NEG_BIG;
                xv[4 * k + 1] = NEG_BIG;
                xv[4 * k + 2] = NEG_BIG;
                xv[4 * k + 3] = NEG_BIG;
            }
        }
#pragma unroll
        for (int k = 0; k < NE; k++) m = fmaxf(m, xv[k]);

        __syncthreads();   // all threads done reading buf

        // ---- kick prefetch of next row (overlaps everything below) ----
        const int nrow = row + stride;
        if (tid == 0 && nrow < ROWS) {
            tma_prefetch_row(buf_u32, X + (size_t)nrow * D, mbar);
        }

        // ---- block max (one-sync) ----
        m = warp_max(m);
        if (lane == 0) red[rb][wid] = m;
        __syncthreads();
        const float max_val = warp_max(red[rb][lane]);
        rb ^= 1;

        // ---- per-thread register compaction of active set {x > max-2} ----
        // valid for tau >= max_val: all other elements give exactly relu(.)=0
        const float thr = max_val - 2.0f;
        float pk0 = NEG_BIG, pk1 = NEG_BIG, pk2 = NEG_BIG, pk3 = NEG_BIG;
        int c = 0;
#pragma unroll
        for (int k = 0; k < NE; k++) {
            float x = xv[k];
            if (x > thr) {
                if      (c == 0) pk0 = x;
                else if (c == 1) pk1 = x;
                else if (c == 2) pk2 = x;
                else if (c == 3) pk3 = x;
                c++;
            }
        }
        const bool full = (c > 4);   // rare per-thread fallback

        // full-row partial sum for one tau (this thread's 32 elements)
        auto part_full = [&](float c2) -> float {
            float a0 = 0.f, a1 = 0.f, a2 = 0.f, a3 = 0.f;
#pragma unroll
            for (int k = 0; k < NE; k += 4) {
                float v0 = fmaxf(fmaf(xv[k + 0], 0.5f, c2), 0.0f);
                float v1 = fmaxf(fmaf(xv[k + 1], 0.5f, c2), 0.0f);
                float v2 = fmaxf(fmaf(xv[k + 2], 0.5f, c2), 0.0f);
                float v3 = fmaxf(fmaf(xv[k + 3], 0.5f, c2), 0.0f);
                a0 = fmaf(v0, v0, a0);
                a1 = fmaf(v1, v1, a1);
                a2 = fmaf(v2, v2, a2);
                a3 = fmaf(v3, v3, a3);
            }
            return (a0 + a1) + (a2 + a3);
        };

        // packed partial sum (only valid when tau >= max_val and !full)
        auto part_packed = [&](float c2) -> float {
            float v0 = fmaxf(fmaf(pk0, 0.5f, c2), 0.0f);
            float v1 = fmaxf(fmaf(pk1, 0.5f, c2), 0.0f);
            float v2 = fmaxf(fmaf(pk2, 0.5f, c2), 0.0f);
            float v3 = fmaxf(fmaf(pk3, 0.5f, c2), 0.0f);
            return fmaf(v0, v0, fmaf(v1, v1, fmaf(v2, v2, v3 * v3)));
        };

        // ---- exact f(tau) for ANY tau (uniform branch on tau) ----
        auto eval = [&](float tau) -> float {
            const float c2 = fmaf(tau, -0.5f, 1.0f);
            float a;
            if (tau >= max_val) {            // block-uniform condition
                a = full ? part_full(c2) : part_packed(c2);
            } else {                          // secant overshot left: exact path
                a = part_full(c2);
            }
            return block_sum(a);
        };

        // ---- fused initial evals (both taus >= max_val by construction) ----
        float lo = max_val;                 // gp(1.0) = 0
        float hi = max_val + HI_OFFSET;
        float f_lo, f_hi;
        {
            const float cl = fmaf(lo, -0.5f, 1.0f);
            const float ch = fmaf(hi, -0.5f, 1.0f);
            float a, b;
            if (full) { a = part_full(cl); b = part_full(ch); }
            else      { a = part_packed(cl); b = part_packed(ch); }
            a = warp_sum(a);
            b = warp_sum(b);
            if (lane == 0) red2[wid] = make_float2(a, b);
            __syncthreads();
            float2 t = red2[lane];
            f_lo = warp_sum(t.x) - 1.0f;
            f_hi = warp_sum(t.y) - 1.0f;
        }

        // ---- secant with early exit (reference carry freezes once
        //      (f_lo - f_hi)^2 < tol, so breaking is exact) ----
#pragma unroll 1
        for (int it = 0; it < MAX_ITER; it++) {
            const float diff = f_lo - f_hi;
            if (diff * diff < TOL) break;
            const float tau = (lo * f_hi - hi * f_lo) / (f_hi - f_lo);
            lo = hi;
            f_lo = f_hi;
            hi = tau;
            f_hi = eval(hi) - 1.0f;
        }

        // ---- write p(X - hi) with streaming stores ----
        float4* y4 = reinterpret_cast<float4*>(Y) + (size_t)row * D4;
        const float c2 = fmaf(hi, -0.5f, 1.0f);
#pragma unroll
        for (int k = 0; k < NV4; k++) {
            const int i4 = tid + k * THREADS;
            if (k < NV4 - 1 || i4 < D4) {
                float v0 = fmaxf(fmaf(xv[4 * k + 0], 0.5f, c2), 0.0f);
                float v1 = fmaxf(fmaf(xv[4 * k + 1], 0.5f, c2), 0.0f);
                float v2 = fmaxf(fmaf(xv[4 * k + 2], 0.5f, c2), 0.0f);
                float v3 = fmaxf(fmaf(xv[4 * k + 3], 0.5f, c2), 0.0f);
                float4 r;
                r.x = v0 * v0;
                r.y = v1 * v1;
                r.z = v2 * v2;
                r.w = v3 * v3;
                __stcs(&y4[i4], r);
            }
        }
        __syncthreads();   // red/red2 reuse fence before next row
    }
}

extern "C" void kernel_launch(void* const* d_in, const int* in_sizes, int n_in,
                              void* d_out, int out_size) {
    const float* X = (const float*)d_in[0];
    float* Y = (float*)d_out;

    static int n_sm = 0;
    if (n_sm == 0) {
        cudaDeviceGetAttribute(&n_sm, cudaDevAttrMultiProcessorCount, 0);
        cudaFuncSetAttribute(tsallis_secant_kernel,
                             cudaFuncAttributeMaxDynamicSharedMemorySize,
                             ROW_BYTES);
    }
    tsallis_secant_kernel<<<n_sm, THREADS, ROW_BYTES>>>(X, Y);
}